// round 15
// baseline (speedup 1.0000x reference)
#include <cuda_runtime.h>

// Trilinear interpolation:
//   img:    [64, 64, 64, 64]  (D, H, W, C) fp32, C contiguous
//   coords: [200000, 3] fp32 in [0, 128)  -> scaled by 1/2 into [0, 64)
//   out:    [200000, 64] fp32
//
// 4 points per warp, 2 per half-warp, software-pipelined:
//   half h (lanes 16h..16h+15) handles ptA = warp*4 + h and ptB = ptA + 2.
//   All 16 corner LDG.128 (A's 8 + B's 8) are front-batched -> 16-deep MLP
//   per lane-stream; A's FMA/store phase overlaps B's in-flight loads.
// Each lane covers 4 channels (float4). Stores: A covers output rows
// {4w, 4w+1} = contiguous 512B; B covers {4w+2, 4w+3}.

#define GRID_H   64
#define CHANNELS 64

struct PointCtx {
    const float4* p[8];
    float w[8];
};

__device__ __forceinline__ PointCtx setup_point(const float* __restrict__ img,
                                                const float* __restrict__ coords,
                                                int pt, int c)
{
    const float x = __ldg(&coords[pt * 3 + 0]) * 0.5f;  // factor = 128/64 = 2
    const float y = __ldg(&coords[pt * 3 + 1]) * 0.5f;
    const float z = __ldg(&coords[pt * 3 + 2]) * 0.5f;

    const float hm1 = (float)(GRID_H - 1);
    const float x1f = floorf(x), x2f = fminf(ceilf(x), hm1);
    const float y1f = floorf(y), y2f = fminf(ceilf(y), hm1);
    const float z1f = floorf(z), z2f = fminf(ceilf(z), hm1);

    // Reference weights: low corner gets (hi - p), high corner gets (p - lo).
    // Degenerate lo==hi: both weights sum to 0, matching the reference.
    const float cx1 = x - x1f, cx0 = x2f - x;
    const float cy1 = y - y1f, cy0 = y2f - y;
    const float cz1 = z - z1f, cz0 = z2f - z;

    const int bx1 = (int)x1f * (GRID_H * GRID_H * CHANNELS);
    const int bx2 = (int)x2f * (GRID_H * GRID_H * CHANNELS);
    const int by1 = (int)y1f * (GRID_H * CHANNELS);
    const int by2 = (int)y2f * (GRID_H * CHANNELS);
    const int bz1 = (int)z1f * CHANNELS;
    const int bz2 = (int)z2f * CHANNELS;

    PointCtx P;
    P.p[0] = (const float4*)(img + bx1 + by1 + bz1 + c);
    P.p[1] = (const float4*)(img + bx2 + by1 + bz1 + c);
    P.p[2] = (const float4*)(img + bx1 + by2 + bz1 + c);
    P.p[3] = (const float4*)(img + bx2 + by2 + bz1 + c);
    P.p[4] = (const float4*)(img + bx1 + by1 + bz2 + c);
    P.p[5] = (const float4*)(img + bx2 + by1 + bz2 + c);
    P.p[6] = (const float4*)(img + bx1 + by2 + bz2 + c);
    P.p[7] = (const float4*)(img + bx2 + by2 + bz2 + c);

    P.w[0] = cx0 * cy0 * cz0;
    P.w[1] = cx1 * cy0 * cz0;
    P.w[2] = cx0 * cy1 * cz0;
    P.w[3] = cx1 * cy1 * cz0;
    P.w[4] = cx0 * cy0 * cz1;
    P.w[5] = cx1 * cy0 * cz1;
    P.w[6] = cx0 * cy1 * cz1;
    P.w[7] = cx1 * cy1 * cz1;
    return P;
}

__device__ __forceinline__ void accum_store(const PointCtx& P, const float4* q,
                                            float* __restrict__ out, int pt, int c)
{
    float ax = P.w[0] * q[0].x, ay = P.w[0] * q[0].y;
    float az = P.w[0] * q[0].z, aw = P.w[0] * q[0].w;
#pragma unroll
    for (int i = 1; i < 8; i++) {
        ax = fmaf(P.w[i], q[i].x, ax);
        ay = fmaf(P.w[i], q[i].y, ay);
        az = fmaf(P.w[i], q[i].z, az);
        aw = fmaf(P.w[i], q[i].w, aw);
    }
    // Streaming store: output is write-once; don't evict the volume from L2.
    __stcs((float4*)(out + pt * CHANNELS + c), make_float4(ax, ay, az, aw));
}

__global__ __launch_bounds__(128)
void proj_trilerp_kernel(const float* __restrict__ img,
                         const float* __restrict__ coords,
                         float* __restrict__ out,
                         int npts)
{
    const int warp = (blockIdx.x * blockDim.x + threadIdx.x) >> 5;
    const int lane = threadIdx.x & 31;
    const int h    = lane >> 4;            // half-warp id
    const int c    = (lane & 15) * 4;      // this lane's 4 channels

    const int ptA = warp * 4 + h;          // output rows {4w, 4w+1} for A
    const int ptB = ptA + 2;               // output rows {4w+2, 4w+3} for B
    if (ptA >= npts) return;

    const PointCtx A = setup_point(img, coords, ptA, c);

    const bool haveB = (ptB < npts);
    // For the tail, clamp B to A's addresses (loads stay in-bounds; result
    // discarded). npts=200000 is divisible by 4, so this path never triggers
    // in practice, but stay correct for any npts.
    const PointCtx B = haveB ? setup_point(img, coords, ptB, c) : A;

    // Front-batch all 16 wide loads: A's 8 first, then B's 8. A's consumers
    // only wait on A; B's loads remain in flight during A's FMA + store.
    float4 qa[8];
#pragma unroll
    for (int i = 0; i < 8; i++) qa[i] = *A.p[i];
    float4 qb[8];
#pragma unroll
    for (int i = 0; i < 8; i++) qb[i] = *B.p[i];

    accum_store(A, qa, out, ptA, c);
    if (haveB) accum_store(B, qb, out, ptB, c);
}

extern "C" void kernel_launch(void* const* d_in, const int* in_sizes, int n_in,
                              void* d_out, int out_size)
{
    const float* img    = (const float*)d_in[0];   // [1,64,64,64,64]
    const float* coords = (const float*)d_in[1];   // [1,200000,3]
    float* out          = (float*)d_out;           // [1,200000,64]

    const int npts = in_sizes[1] / 3;              // 200000

    // 4 points per warp, 4 warps per block -> 16 points per block
    const int pts_per_block = 16;
    const int blocks = (npts + pts_per_block - 1) / pts_per_block;
    proj_trilerp_kernel<<<blocks, 128>>>(img, coords, out, npts);
}